// round 4
// baseline (speedup 1.0000x reference)
#include <cuda_runtime.h>

// ConvKB scoring: score[e] = sum_{c,d} relu(w0c*h[row,d] + w1c*h[col,d] + w2c*g[t,d] + bc) * lin_w[c*D+d] + lin_b
// E=50000, D=128, C=32. FMA-pipe bound -> packed f32x2 FMA; relu via (t+|t|) with lin_w pre-scaled by 0.5.
// Index arrays may be int32 (JAX x64-disabled demotion) or int64 -> runtime-detected.

#define D 128
#define C 32
#define THREADS 128          // 4 warps = 2 edge slots per block
#define BLOCKS  592

typedef unsigned long long ull;

__device__ int g_is64;       // 1 if edge_idx/edge_type are int64, 0 if int32

__device__ __forceinline__ ull ffma2(ull a, ull b, ull c) {
    ull d;
    asm("fma.rn.f32x2 %0, %1, %2, %3;" : "=l"(d) : "l"(a), "l"(b), "l"(c));
    return d;
}
// returns 2*relu(a) packed: a + |a|
__device__ __forceinline__ ull relu2x2(ull a) {
    ull ab = a & 0x7FFFFFFF7FFFFFFFULL;
    ull d;
    asm("add.rn.f32x2 %0, %1, %2;" : "=l"(d) : "l"(a), "l"(ab));
    return d;
}
__device__ __forceinline__ ull pack2(float lo, float hi) {
    ull d;
    asm("mov.b64 %0, {%1, %2};" : "=l"(d) : "f"(lo), "f"(hi));
    return d;
}
__device__ __forceinline__ float2 unpack2(ull v) {
    float2 r;
    asm("mov.b64 {%0, %1}, %2;" : "=f"(r.x), "=f"(r.y) : "l"(v));
    return r;
}

// If int64 little-endian with values < 2^31, every odd int32 word is 0.
__global__ void detect_idx_kernel(const int* __restrict__ ei) {
    int is64 = 1;
    for (int i = 1; i < 128; i += 2)
        if (ei[i] != 0) { is64 = 0; break; }
    g_is64 = is64;
}

__global__ void __launch_bounds__(THREADS, 4) convkb_kernel(
    const float* __restrict__ h,
    const float* __restrict__ g,
    const int* __restrict__ edge_idx,    // [2, E], int32 or int64 (low words read)
    const int* __restrict__ edge_type,   // [E]
    const float* __restrict__ conv_w,    // [C,3]
    const float* __restrict__ conv_b,    // [C]
    const float* __restrict__ lin_w,     // [C*D]
    const float* __restrict__ lin_b,     // [1]
    float* __restrict__ out,             // [E]
    int E)
{
    // Pre-packed conv params in smem: per channel c: {w0,w0},{w1,w1},{w2,w2},{b,b}
    __shared__ alignas(16) ull sm_par[C * 4];
    __shared__ float part[THREADS / 32];

    const int tid  = threadIdx.x;
    const int warp = tid >> 5;
    const int lane = tid & 31;
    const int slot = warp >> 1;       // 2 edge slots per block
    const int half = warp & 1;        // which 64-d half of the edge

    const int stride = g_is64 ? 2 : 1;   // int32 elements per logical index

    if (tid < C) {
        const int c = tid;
        float w0 = conv_w[3 * c + 0];
        float w1 = conv_w[3 * c + 1];
        float w2 = conv_w[3 * c + 2];
        float b  = conv_b[c];
        sm_par[4 * c + 0] = pack2(w0, w0);
        sm_par[4 * c + 1] = pack2(w1, w1);
        sm_par[4 * c + 2] = pack2(w2, w2);
        sm_par[4 * c + 3] = pack2(b, b);
    }

    // Register-resident lin_w slice, pre-scaled by 0.5 (relu trick gives 2*relu).
    const int dbase = half * 32 + lane;   // float2 index within the 64-float2 row
    ull lw[C];
    {
        const float2* lwp = (const float2*)lin_w;
#pragma unroll
        for (int c = 0; c < C; ++c) {
            float2 t = lwp[c * (D / 2) + dbase];
            lw[c] = pack2(0.5f * t.x, 0.5f * t.y);
        }
    }
    const float lb = lin_b[0];
    __syncthreads();

    const int num_slots = gridDim.x * 2;
    const int iters = (E + num_slots - 1) / num_slots;   // uniform across block

    const ulonglong2* par2 = (const ulonglong2*)sm_par;

    for (int it = 0; it < iters; ++it) {
        const int e = it * num_slots + (int)blockIdx.x * 2 + slot;
        if (e < E) {
            const int row = edge_idx[(size_t)stride * e];
            const int col = edge_idx[(size_t)stride * (E + e)];
            const int rel = edge_type[(size_t)stride * e];

            const float2* up = (const float2*)(h + (size_t)row * D);
            const float2* vp = (const float2*)(h + (size_t)col * D);
            const float2* rp = (const float2*)(g + (size_t)rel * D);

            float2 uf = up[dbase];
            float2 vf = vp[dbase];
            float2 rf = rp[dbase];
            ull u2 = pack2(uf.x, uf.y);
            ull v2 = pack2(vf.x, vf.y);
            ull r2 = pack2(rf.x, rf.y);

            ull acc = 0ULL;   // packed {0.f, 0.f}
#pragma unroll
            for (int c = 0; c < C; ++c) {
                ulonglong2 pa = par2[2 * c + 0];   // {w0w0, w1w1}
                ulonglong2 pb = par2[2 * c + 1];   // {w2w2, bb}
                ull t = ffma2(pb.x, r2, pb.y);     // w2*r + b
                t = ffma2(pa.y, v2, t);            // + w1*v
                t = ffma2(pa.x, u2, t);            // + w0*u
                t = relu2x2(t);                    // 2*relu(t)
                acc = ffma2(t, lw[c], acc);        // lw pre-scaled by 0.5
            }
            float2 a = unpack2(acc);
            float s = a.x + a.y;
#pragma unroll
            for (int off = 16; off > 0; off >>= 1)
                s += __shfl_xor_sync(0xffffffffu, s, off);
            if (lane == 0) part[warp] = s;
        }
        __syncthreads();
        if (tid < 2) {
            const int e2 = it * num_slots + (int)blockIdx.x * 2 + tid;
            if (e2 < E)
                out[e2] = part[2 * tid] + part[2 * tid + 1] + lb;
        }
        __syncthreads();
    }
}

extern "C" void kernel_launch(void* const* d_in, const int* in_sizes, int n_in,
                              void* d_out, int out_size) {
    // Identify inputs by unique element counts (immune to metadata ordering).
    const float *h = 0, *g = 0, *conv_w = 0, *conv_b = 0, *lin_w = 0, *lin_b = 0;
    const int *edge_idx = 0, *edge_type = 0;
    for (int i = 0; i < n_in; ++i) {
        switch (in_sizes[i]) {
            case 50000 * 128: h         = (const float*)d_in[i]; break;
            case 500 * 128:   g         = (const float*)d_in[i]; break;
            case 100000:      edge_idx  = (const int*)d_in[i];   break;
            case 50000:       edge_type = (const int*)d_in[i];   break;
            case 96:          conv_w    = (const float*)d_in[i]; break;
            case 32:          conv_b    = (const float*)d_in[i]; break;
            case 4096:        lin_w     = (const float*)d_in[i]; break;
            case 1:           lin_b     = (const float*)d_in[i]; break;
            default: break;
        }
    }
    float* out = (float*)d_out;
    const int E = 50000;

    detect_idx_kernel<<<1, 1>>>(edge_idx);
    convkb_kernel<<<BLOCKS, THREADS>>>(h, g, edge_idx, edge_type,
                                       conv_w, conv_b, lin_w, lin_b, out, E);
}

// round 5
// speedup vs baseline: 1.0994x; 1.0994x over previous
#include <cuda_runtime.h>

// ConvKB: score[e] = sum_{c,d} relu(w0c*u_d + w1c*v_d + w2c*r_d + bc) * lw[c,d] + lb
// E=50000, D=128, C=32. FMA-pipe bound. Channel-pair packed f32x2 FMA, all params
// register-resident, zero shared-memory traffic in the loop, warp-per-(edge,half)
// with 2-way commutative atomicAdd. relu via (t+|t|), lw pre-scaled by 0.5.

#define D 128
#define C 32
#define THREADS 128
#define BLOCKS 296            // 148 SMs * 2 blocks (2/SM at ~200 regs)
#define NEDGE 50000
#define TASKS (2 * NEDGE)     // (edge, channel-half) tasks
#define CP 8                  // channel-pairs per warp (16 channels)

typedef unsigned long long ull;

__device__ int g_is64;        // 1 if index arrays are int64, 0 if int32

__device__ __forceinline__ ull ffma2(ull a, ull b, ull c) {
    ull d;
    asm("fma.rn.f32x2 %0, %1, %2, %3;" : "=l"(d) : "l"(a), "l"(b), "l"(c));
    return d;
}
__device__ __forceinline__ ull fadd2(ull a, ull b) {
    ull d;
    asm("add.rn.f32x2 %0, %1, %2;" : "=l"(d) : "l"(a), "l"(b));
    return d;
}
// 2*relu(a) packed: a + |a|
__device__ __forceinline__ ull relu2x2(ull a) {
    return fadd2(a, a & 0x7FFFFFFF7FFFFFFFULL);
}
__device__ __forceinline__ ull pack2(float lo, float hi) {
    ull d;
    asm("mov.b64 %0, {%1, %2};" : "=l"(d) : "f"(lo), "f"(hi));
    return d;
}
__device__ __forceinline__ float2 unpack2(ull v) {
    float2 r;
    asm("mov.b64 {%0, %1}, %2;" : "=f"(r.x), "=f"(r.y) : "l"(v));
    return r;
}

// Fused: dtype detection (thread 0) + out[] init to lin_b.
__global__ void init_kernel(float* __restrict__ out, const float* __restrict__ lin_b,
                            const int* __restrict__ ei) {
    int i = blockIdx.x * blockDim.x + threadIdx.x;
    if (i == 0) {
        int is64 = 1;
        for (int k = 1; k < 128; k += 2)
            if (ei[k] != 0) { is64 = 0; break; }
        g_is64 = is64;
    }
    if (i < NEDGE) out[i] = lin_b[0];
}

__global__ void __launch_bounds__(THREADS, 2) convkb_kernel(
    const float* __restrict__ h,
    const float* __restrict__ g,
    const int* __restrict__ edge_idx,    // [2,E], low int32 words read
    const int* __restrict__ edge_type,   // [E]
    const float* __restrict__ conv_w,    // [C,3]
    const float* __restrict__ conv_b,    // [C]
    const float* __restrict__ lin_w,     // [C*D]
    float* __restrict__ out)             // [E], pre-initialized to lin_b
{
    const int lane = threadIdx.x & 31;
    const int warp = threadIdx.x >> 5;
    const int wg   = (int)blockIdx.x * (THREADS / 32) + warp;   // global warp id
    const int TW   = BLOCKS * (THREADS / 32);                   // total warps (even)
    const int half = wg & 1;            // constant: TW even -> task parity fixed
    const int stride = g_is64 ? 2 : 1;

    // ---- Edge-invariant register state ----
    // conv params, channel-pair packed: pair cp covers channels c0=half*16+2cp, c1=c0+1
    ull w0p[CP], w1p[CP], w2p[CP], bp[CP];
#pragma unroll
    for (int cp = 0; cp < CP; ++cp) {
        int c0 = half * 16 + 2 * cp, c1 = c0 + 1;
        w0p[cp] = pack2(conv_w[3 * c0 + 0], conv_w[3 * c1 + 0]);
        w1p[cp] = pack2(conv_w[3 * c0 + 1], conv_w[3 * c1 + 1]);
        w2p[cp] = pack2(conv_w[3 * c0 + 2], conv_w[3 * c1 + 2]);
        bp[cp]  = pack2(conv_b[c0], conv_b[c1]);
    }
    // lin_w slice, pre-scaled 0.5 (relu trick yields 2*relu).
    // This lane's d values: 2L, 2L+1, 2L+64, 2L+65  (L=lane)
    ull lw[CP][4];
    {
        const float2* lwp = (const float2*)lin_w;
#pragma unroll
        for (int cp = 0; cp < CP; ++cp) {
            int c0 = half * 16 + 2 * cp, c1 = c0 + 1;
            float2 a0 = lwp[c0 * 64 + lane],      a1 = lwp[c1 * 64 + lane];
            float2 b0 = lwp[c0 * 64 + lane + 32], b1 = lwp[c1 * 64 + lane + 32];
            lw[cp][0] = pack2(0.5f * a0.x, 0.5f * a1.x);
            lw[cp][1] = pack2(0.5f * a0.y, 0.5f * a1.y);
            lw[cp][2] = pack2(0.5f * b0.x, 0.5f * b1.x);
            lw[cp][3] = pack2(0.5f * b0.y, 0.5f * b1.y);
        }
    }

    const int iters = (TASKS + TW - 1) / TW;

    // ---- Preload first task's gathers ----
    int t = wg;
    bool curv = true;
    int e = t >> 1;
    float2 cu0, cu1, cv0, cv1, cr0, cr1;
    {
        int row = edge_idx[(size_t)stride * e];
        int col = edge_idx[(size_t)stride * (NEDGE + e)];
        int rel = edge_type[(size_t)stride * e];
        const float2* up = (const float2*)(h + (size_t)row * D);
        const float2* vp = (const float2*)(h + (size_t)col * D);
        const float2* rp = (const float2*)(g + (size_t)rel * D);
        cu0 = up[lane]; cu1 = up[lane + 32];
        cv0 = vp[lane]; cv1 = vp[lane + 32];
        cr0 = rp[lane]; cr1 = rp[lane + 32];
    }

    for (int it = 0; it < iters; ++it) {
        // ---- Prefetch next task (clamped to a safe address) ----
        int tn = t + TW;
        bool nv = tn < TASKS;
        int ts = nv ? tn : t;
        int es = ts >> 1;
        float2 nu0, nu1, nv0, nv1, nr0, nr1;
        {
            int row = edge_idx[(size_t)stride * es];
            int col = edge_idx[(size_t)stride * (NEDGE + es)];
            int rel = edge_type[(size_t)stride * es];
            const float2* up = (const float2*)(h + (size_t)row * D);
            const float2* vp = (const float2*)(h + (size_t)col * D);
            const float2* rp = (const float2*)(g + (size_t)rel * D);
            nu0 = up[lane]; nu1 = up[lane + 32];
            nv0 = vp[lane]; nv1 = vp[lane + 32];
            nr0 = rp[lane]; nr1 = rp[lane + 32];
        }

        // ---- Compute current task ----
        ull ud0 = pack2(cu0.x, cu0.x), ud1 = pack2(cu0.y, cu0.y);
        ull ud2 = pack2(cu1.x, cu1.x), ud3 = pack2(cu1.y, cu1.y);
        ull vd0 = pack2(cv0.x, cv0.x), vd1 = pack2(cv0.y, cv0.y);
        ull vd2 = pack2(cv1.x, cv1.x), vd3 = pack2(cv1.y, cv1.y);
        ull rd0 = pack2(cr0.x, cr0.x), rd1 = pack2(cr0.y, cr0.y);
        ull rd2 = pack2(cr1.x, cr1.x), rd3 = pack2(cr1.y, cr1.y);

        ull acc0 = 0ULL, acc1 = 0ULL, acc2 = 0ULL, acc3 = 0ULL;
#pragma unroll
        for (int cp = 0; cp < CP; ++cp) {
            ull t0 = ffma2(w2p[cp], rd0, bp[cp]);
            ull t1 = ffma2(w2p[cp], rd1, bp[cp]);
            ull t2 = ffma2(w2p[cp], rd2, bp[cp]);
            ull t3 = ffma2(w2p[cp], rd3, bp[cp]);
            t0 = ffma2(w1p[cp], vd0, t0);
            t1 = ffma2(w1p[cp], vd1, t1);
            t2 = ffma2(w1p[cp], vd2, t2);
            t3 = ffma2(w1p[cp], vd3, t3);
            t0 = ffma2(w0p[cp], ud0, t0);
            t1 = ffma2(w0p[cp], ud1, t1);
            t2 = ffma2(w0p[cp], ud2, t2);
            t3 = ffma2(w0p[cp], ud3, t3);
            t0 = relu2x2(t0);
            t1 = relu2x2(t1);
            t2 = relu2x2(t2);
            t3 = relu2x2(t3);
            acc0 = ffma2(t0, lw[cp][0], acc0);
            acc1 = ffma2(t1, lw[cp][1], acc1);
            acc2 = ffma2(t2, lw[cp][2], acc2);
            acc3 = ffma2(t3, lw[cp][3], acc3);
        }
        acc0 = fadd2(acc0, acc1);
        acc2 = fadd2(acc2, acc3);
        acc0 = fadd2(acc0, acc2);
        float2 a = unpack2(acc0);
        float s = a.x + a.y;
#pragma unroll
        for (int off = 16; off > 0; off >>= 1)
            s += __shfl_xor_sync(0xffffffffu, s, off);
        if (curv && lane == 0)
            atomicAdd(out + e, s);

        // ---- Advance ----
        t = ts; e = es; curv = nv;
        cu0 = nu0; cu1 = nu1; cv0 = nv0; cv1 = nv1; cr0 = nr0; cr1 = nr1;
    }
}

extern "C" void kernel_launch(void* const* d_in, const int* in_sizes, int n_in,
                              void* d_out, int out_size) {
    // Identify inputs by unique element counts (immune to metadata ordering).
    const float *h = 0, *g = 0, *conv_w = 0, *conv_b = 0, *lin_w = 0, *lin_b = 0;
    const int *edge_idx = 0, *edge_type = 0;
    for (int i = 0; i < n_in; ++i) {
        switch (in_sizes[i]) {
            case NEDGE * 128: h         = (const float*)d_in[i]; break;
            case 500 * 128:   g         = (const float*)d_in[i]; break;
            case 2 * NEDGE:   edge_idx  = (const int*)d_in[i];   break;
            case NEDGE:       edge_type = (const int*)d_in[i];   break;
            case 96:          conv_w    = (const float*)d_in[i]; break;
            case 32:          conv_b    = (const float*)d_in[i]; break;
            case 4096:        lin_w     = (const float*)d_in[i]; break;
            case 1:           lin_b     = (const float*)d_in[i]; break;
            default: break;
        }
    }
    float* out = (float*)d_out;

    init_kernel<<<(NEDGE + 255) / 256, 256>>>(out, lin_b, edge_idx);
    convkb_kernel<<<BLOCKS, THREADS>>>(h, g, edge_idx, edge_type,
                                       conv_w, conv_b, lin_w, out);
}